// round 15
// baseline (speedup 1.0000x reference)
#include <cuda_runtime.h>
#include <cstdint>

// Problem dims
#define PD1   128
#define PD2   128
#define PB    16
#define PSIN  64
#define PSOUT 128
// a / h layout: [i][j][b][s] row-major, s fastest.
// float offset = i*262144 + j*2048 + b*128 + s

typedef unsigned long long ull_t;

__device__ __forceinline__ ull_t pack2(float x) {
    unsigned int xi = __float_as_uint(x);
    ull_t r;
    asm("mov.b64 %0, {%1, %1};" : "=l"(r) : "r"(xi));
    return r;
}
__device__ __forceinline__ void ffma2(ull_t &d, ull_t a, ull_t b) {
    asm("fma.rn.f32x2 %0, %1, %2, %0;" : "+l"(d) : "l"(a), "l"(b));
}
__device__ __forceinline__ float tanh_mufu(float z) {
    float r;
    asm("tanh.approx.f32 %0, %1;" : "=f"(r) : "f"(z));
    return r;
}

// ---------------- Kernel 1: a = x @ w + bias  (into d_out) ----------------
// Measured ~91-94us: 128m x 128n tile, 256 threads, micro-tile 8m x 8n
// (4 f32x2 segs), K=64 in two 32-wide phases. Unchanged (known-good).
// NOTE: tcgen05 is NOT available in this build (harness lowers via
// compute_103 PTX; ptxas rejects tcgen05 on plain sm_103) — FFMA2 it is.
#define XS_LD 36
__global__ __launch_bounds__(256)
void mdrnn_gemm_kernel(const float* __restrict__ X, const float* __restrict__ W,
                       const float* __restrict__ Bias, float* __restrict__ A) {
    __shared__ float xs[128 * XS_LD];   // 18432 B
    __shared__ float ws[32 * 128];      // 16384 B

    const int tid   = threadIdx.x;
    const int mtile = blockIdx.x;                 // 2048 tiles of 128 rows
    const float* Xb = X + (size_t)mtile * 128 * PSIN;

    const int tidm = tid >> 4;
    const int tidn = tid & 15;
    const int m0   = tidm * 8;
    const int n0   = tidn * 2;

    ull_t acc[8][4];
#pragma unroll
    for (int mi = 0; mi < 8; mi++)
#pragma unroll
        for (int seg = 0; seg < 4; seg++) acc[mi][seg] = 0ULL;

    for (int kk = 0; kk < PSIN; kk += 32) {
        __syncthreads();
#pragma unroll
        for (int q = 0; q < 4; q++) {
            int id  = tid + 256 * q;
            int row = id >> 3;
            int kq  = id & 7;
            *(float4*)&xs[row * XS_LD + kq * 4] =
                *(const float4*)(Xb + row * PSIN + kk + kq * 4);
        }
#pragma unroll
        for (int q = 0; q < 4; q++) {
            int id = tid + 256 * q;
            int k  = id >> 5;
            int nq = id & 31;
            *(float4*)&ws[k * 128 + nq * 4] =
                *(const float4*)(W + (size_t)(kk + k) * PSOUT + nq * 4);
        }
        __syncthreads();

#pragma unroll 4
        for (int k = 0; k < 32; k++) {
            ull_t wv[4];
#pragma unroll
            for (int seg = 0; seg < 4; seg++)
                wv[seg] = *(const ull_t*)&ws[k * 128 + n0 + seg * 32];
#pragma unroll
            for (int mi = 0; mi < 8; mi++) {
                ull_t xp = pack2(xs[(m0 + mi) * XS_LD + k]);
#pragma unroll
                for (int seg = 0; seg < 4; seg++) ffma2(acc[mi][seg], xp, wv[seg]);
            }
        }
    }

    float2 bv[4];
#pragma unroll
    for (int seg = 0; seg < 4; seg++)
        bv[seg] = *(const float2*)(Bias + n0 + seg * 32);

#pragma unroll
    for (int mi = 0; mi < 8; mi++) {
        float* out = A + ((size_t)mtile * 128 + m0 + mi) * PSOUT;
#pragma unroll
        for (int seg = 0; seg < 4; seg++) {
            uint2 u = *(uint2*)&acc[mi][seg];
            float2 o;
            o.x = __uint_as_float(u.x) + bv[seg].x;
            o.y = __uint_as_float(u.y) + bv[seg].y;
            *(float2*)(out + n0 + seg * 32) = o;
        }
    }
}

// ---------------- Kernel 2: chunked wavefront scan, 4 cols/step -------------
// 128 blocks x 512 threads. Block = (b, 16-wide s chunk); thread = (row i,
// s-quad). At step t, active threads (0 <= t-i < 32) process 4 columns
// jb..jb+3 where jb = 4*(t-i), serially (left-dep in register). Row skew is
// 1 step: row i-1 at step t-1 produced exactly cols 4(t-i)..4(t-i)+3, handed
// via double-buffered dynamic smem sh[buf][col][row][qd] (contiguous 512B per
// warp access -> conflict-free). Steps: 159 (vs 255 at 1 col/step) -> less
// barrier + chain overhead, same total L1 wavefronts.
// Prefetch: register double-buffer r0/r1 (4 cols each), consumed 2 steps
// after issue (~800cyc distance). Seeds cover the first 2 active steps, and
// refills start at activation -> no coverage gap.
#define SC_SMEM 65536
__global__ __launch_bounds__(512)
void mdrnn_scan_kernel(const float* __restrict__ U, float* __restrict__ H) {
    extern __shared__ float4 sh[];   // [buf 2][col 4][row 128][qd 4]

    const int tid = threadIdx.x;
    const int i   = tid >> 2;            // row 0..127
    const int qd  = tid & 3;             // s-quad 0..3
    const int b   = blockIdx.x >> 3;     // 0..15
    const int sc  = blockIdx.x & 7;      // 0..7
    const int s0  = sc * 16 + qd * 4;

    const float4 u0 = *(const float4*)(U + s0);
    const float4 u1 = *(const float4*)(U + PSOUT + s0);

    float* Hrow = H + (size_t)i * 262144 + (size_t)b * PSOUT + s0;  // + j*2048

    // seeds: r0 = cols 0..3 (first active step), r1 = cols 4..7 (second)
    float4 r0[4], r1[4];
#pragma unroll
    for (int c = 0; c < 4; c++) {
        r0[c] = *(const float4*)(Hrow + (size_t)c * 2048);
        r1[c] = *(const float4*)(Hrow + (size_t)(c + 4) * 2048);
    }

    float4 h = make_float4(0.f, 0.f, 0.f, 0.f);   // h[i][last col processed]

#pragma unroll 2
    for (int t = 0; t < 159; t++) {
        const int d = t - i;
        if ((unsigned)d < 32u) {
            const int jb = 4 * d;

            // fetch up-row h for all 4 columns (written by row i-1 at t-1)
            float4 qa[4];
            if (i == 0) {
#pragma unroll
                for (int c = 0; c < 4; c++)
                    qa[c] = make_float4(0.f, 0.f, 0.f, 0.f);
            } else {
                const int rb = ((t & 1) ^ 1) * 4;
#pragma unroll
                for (int c = 0; c < 4; c++)
                    qa[c] = sh[((rb + c) * 128 + (i - 1)) * 4 + qd];
            }

            // consume r0, rotate r1 -> r0, refill r1 with cols jb+8..jb+11
            float4 cur[4];
#pragma unroll
            for (int c = 0; c < 4; c++) { cur[c] = r0[c]; r0[c] = r1[c]; }
            const int jf = jb + 8;
            if (jf < 128) {
#pragma unroll
                for (int c = 0; c < 4; c++)
                    r1[c] = *(const float4*)(Hrow + (size_t)(jf + c) * 2048);
            }

            // 4 columns, serial in h (left dependency)
            const int wb = (t & 1) * 4;
#pragma unroll
            for (int c = 0; c < 4; c++) {
                float4 z;
                z.x = fmaf(qa[c].x, u0.x, cur[c].x); z.x = fmaf(h.x, u1.x, z.x);
                z.y = fmaf(qa[c].y, u0.y, cur[c].y); z.y = fmaf(h.y, u1.y, z.y);
                z.z = fmaf(qa[c].z, u0.z, cur[c].z); z.z = fmaf(h.z, u1.z, z.z);
                z.w = fmaf(qa[c].w, u0.w, cur[c].w); z.w = fmaf(h.w, u1.w, z.w);
                h.x = tanh_mufu(z.x); h.y = tanh_mufu(z.y);
                h.z = tanh_mufu(z.z); h.w = tanh_mufu(z.w);
                sh[((wb + c) * 128 + i) * 4 + qd] = h;
                *(float4*)(Hrow + (size_t)(jb + c) * 2048) = h;
            }
        }
        __syncthreads();
    }
}

// ---------------- launch ----------------
extern "C" void kernel_launch(void* const* d_in, const int* in_sizes, int n_in,
                              void* d_out, int out_size) {
    const float* X    = (const float*)d_in[0];   // (128,128,16,64)
    const float* W    = (const float*)d_in[1];   // (64,128)
    const float* U    = (const float*)d_in[2];   // (2,128)
    const float* Bias = (const float*)d_in[3];   // (128,)
    float* H = (float*)d_out;                    // (128,128,16,128) — holds a, then h

    (void)in_sizes; (void)n_in; (void)out_size;

    cudaFuncSetAttribute(mdrnn_scan_kernel,
                         cudaFuncAttributeMaxDynamicSharedMemorySize, SC_SMEM);

    mdrnn_gemm_kernel<<<2048, 256>>>(X, W, Bias, H);
    mdrnn_scan_kernel<<<128, 512, SC_SMEM>>>(U, H);
}

// round 16
// speedup vs baseline: 1.8920x; 1.8920x over previous
#include <cuda_runtime.h>
#include <cstdint>

// Problem dims
#define PD1   128
#define PD2   128
#define PB    16
#define PSIN  64
#define PSOUT 128
// a / h layout: [i][j][b][s] row-major, s fastest.
// float offset = i*262144 + j*2048 + b*128 + s

typedef unsigned long long ull_t;

__device__ __forceinline__ void ffma2(ull_t &d, ull_t a, ull_t b) {
    asm("fma.rn.f32x2 %0, %1, %2, %0;" : "+l"(d) : "l"(a), "l"(b));
}
__device__ __forceinline__ float tanh_mufu(float z) {
    float r;
    asm("tanh.approx.f32 %0, %1;" : "=f"(r) : "f"(z));
    return r;
}

// ---------------- Kernel 1: a = x @ w + bias  (into d_out) ----------------
// 128m x 128n tile, 256 threads, micro-tile 8m x 8n (4 f32x2 segs), K=64 in
// two 32-wide phases. CHANGE vs R7 (94us): X stored in smem pre-duplicated
// as (x,x) 64-bit pairs — duplication done via register reuse in the STS.128
// data (no movs). Inner loop: 4 LDS.64 (w) + 8 LDS.64 (x bcast) + 32 FFMA2
// = 44 issues/k (was 52 incl. 8 pack movs).
#define KST 34   // xs2 row stride in ULL (272B): ~2-way store conflicts max
__global__ __launch_bounds__(256)
void mdrnn_gemm_kernel(const float* __restrict__ X, const float* __restrict__ W,
                       const float* __restrict__ Bias, float* __restrict__ A) {
    __shared__ ull_t xs2[128 * KST];    // 34816 B
    __shared__ float ws[32 * 128];      // 16384 B

    const int tid   = threadIdx.x;
    const int mtile = blockIdx.x;                 // 2048 tiles of 128 rows
    const float* Xb = X + (size_t)mtile * 128 * PSIN;

    const int tidm = tid >> 4;        // 0..15 -> m0 = tidm*8
    const int tidn = tid & 15;        // 0..15 -> n  = tidn*2 + seg*32
    const int m0   = tidm * 8;
    const int n0   = tidn * 2;

    ull_t acc[8][4];
#pragma unroll
    for (int mi = 0; mi < 8; mi++)
#pragma unroll
        for (int seg = 0; seg < 4; seg++) acc[mi][seg] = 0ULL;

    for (int kk = 0; kk < PSIN; kk += 32) {
        __syncthreads();
        // x half-tile: 128 rows x 32 k = 1024 float4, 4 per thread,
        // stored duplicated: float4 -> 4 ULL (x,x) -> 2 STS.128
#pragma unroll
        for (int q = 0; q < 4; q++) {
            int id  = tid + 256 * q;
            int row = id >> 3;
            int kq  = id & 7;
            float4 v = *(const float4*)(Xb + row * PSIN + kk + kq * 4);
            uint32_t ux = __float_as_uint(v.x), uy = __float_as_uint(v.y);
            uint32_t uz = __float_as_uint(v.z), uw = __float_as_uint(v.w);
            uint4* p = (uint4*)&xs2[row * KST + kq * 4];
            p[0] = make_uint4(ux, ux, uy, uy);
            p[1] = make_uint4(uz, uz, uw, uw);
        }
        // w half-tile: 32 k x 128 n = 1024 float4, 4 per thread
#pragma unroll
        for (int q = 0; q < 4; q++) {
            int id = tid + 256 * q;
            int k  = id >> 5;
            int nq = id & 31;
            *(float4*)&ws[k * 128 + nq * 4] =
                *(const float4*)(W + (size_t)(kk + k) * PSOUT + nq * 4);
        }
        __syncthreads();

#pragma unroll 4
        for (int k = 0; k < 32; k++) {
            ull_t wv[4];
#pragma unroll
            for (int seg = 0; seg < 4; seg++)
                wv[seg] = *(const ull_t*)&ws[k * 128 + n0 + seg * 32];
#pragma unroll
            for (int mi = 0; mi < 8; mi++) {
                ull_t xp = xs2[(m0 + mi) * KST + k];   // LDS.64, 16-lane bcast
#pragma unroll
                for (int seg = 0; seg < 4; seg++) ffma2(acc[mi][seg], xp, wv[seg]);
            }
        }
    }

    float2 bv[4];
#pragma unroll
    for (int seg = 0; seg < 4; seg++)
        bv[seg] = *(const float2*)(Bias + n0 + seg * 32);

#pragma unroll
    for (int mi = 0; mi < 8; mi++) {
        float* out = A + ((size_t)mtile * 128 + m0 + mi) * PSOUT;
#pragma unroll
        for (int seg = 0; seg < 4; seg++) {
            uint2 u = *(uint2*)&acc[mi][seg];
            float2 o;
            o.x = __uint_as_float(u.x) + bv[seg].x;
            o.y = __uint_as_float(u.y) + bv[seg].y;
            *(float2*)(out + n0 + seg * 32) = o;
        }
    }
}

// ---------------- Kernel 2: 16-warp wavefront scan, 4 threads/row -----------
// EXACT R12 version (measured 71.8us). 128 blocks x 512 threads.
#define SDEPTH 8
__global__ __launch_bounds__(512)
void mdrnn_scan_kernel(const float* __restrict__ U, float* __restrict__ H) {
    __shared__ float4 sh[2][128][4];   // [buf][row][quad], 16KB

    const int tid = threadIdx.x;
    const int i   = tid >> 2;            // row 0..127
    const int qd  = tid & 3;             // s-quad 0..3
    const int b   = blockIdx.x >> 3;     // 0..15
    const int sc  = blockIdx.x & 7;      // 0..7
    const int s0  = sc * 16 + qd * 4;

    const float4 u0 = *(const float4*)(U + s0);
    const float4 u1 = *(const float4*)(U + PSOUT + s0);

    float* Hrow = H + (size_t)i * 262144 + (size_t)b * PSOUT + s0;  // + j*2048

    float4 ra[SDEPTH];
#pragma unroll
    for (int q = 0; q < SDEPTH; q++) {
        int j = q - i;
        if ((unsigned)j < 128u)
            ra[q] = *(const float4*)(Hrow + (size_t)j * 2048);
    }

    float4 h = make_float4(0.f, 0.f, 0.f, 0.f);

#pragma unroll 8
    for (int t = 0; t < 256; t++) {
        const int j    = t - i;
        const int slot = t & (SDEPTH - 1);

        float4 aa = ra[slot];
        int jf = t + SDEPTH - i;
        if ((unsigned)jf < 128u)
            ra[slot] = *(const float4*)(Hrow + (size_t)jf * 2048);

        if ((unsigned)j < 128u) {
            float4 qa;
            if (i == 0) {
                qa = make_float4(0.f, 0.f, 0.f, 0.f);
            } else {
                qa = sh[(t & 1) ^ 1][i - 1][qd];
            }

            float4 z;
            z.x = fmaf(qa.x, u0.x, aa.x); z.x = fmaf(h.x, u1.x, z.x);
            z.y = fmaf(qa.y, u0.y, aa.y); z.y = fmaf(h.y, u1.y, z.y);
            z.z = fmaf(qa.z, u0.z, aa.z); z.z = fmaf(h.z, u1.z, z.z);
            z.w = fmaf(qa.w, u0.w, aa.w); z.w = fmaf(h.w, u1.w, z.w);

            h.x = tanh_mufu(z.x); h.y = tanh_mufu(z.y);
            h.z = tanh_mufu(z.z); h.w = tanh_mufu(z.w);

            sh[t & 1][i][qd] = h;
            *(float4*)(Hrow + (size_t)j * 2048) = h;
        }
        __syncthreads();
    }
}

// ---------------- launch ----------------
extern "C" void kernel_launch(void* const* d_in, const int* in_sizes, int n_in,
                              void* d_out, int out_size) {
    const float* X    = (const float*)d_in[0];   // (128,128,16,64)
    const float* W    = (const float*)d_in[1];   // (64,128)
    const float* U    = (const float*)d_in[2];   // (2,128)
    const float* Bias = (const float*)d_in[3];   // (128,)
    float* H = (float*)d_out;                    // (128,128,16,128) — holds a, then h

    (void)in_sizes; (void)n_in; (void)out_size;

    mdrnn_gemm_kernel<<<2048, 256>>>(X, W, Bias, H);
    mdrnn_scan_kernel<<<128, 512>>>(U, H);
}

// round 17
// speedup vs baseline: 2.0567x; 1.0870x over previous
#include <cuda_runtime.h>
#include <cuda_fp16.h>
#include <cstdint>

// Problem dims
#define PD1   128
#define PD2   128
#define PB    16
#define PSIN  64
#define PSOUT 128
// h layout: [i][j][b][s] row-major, s fastest.
// float offset = i*262144 + j*2048 + b*128 + s

typedef unsigned long long ull_t;

// Static scratch: a = x@w + bias stored as fp16 (64 MB). Allowed per the
// allocation rules (__device__ global array). Separate from d_out -> no
// in-place aliasing in the scan.
__device__ __half A16[33554432];

__device__ __forceinline__ ull_t pack2(float x) {
    unsigned int xi = __float_as_uint(x);
    ull_t r;
    asm("mov.b64 %0, {%1, %1};" : "=l"(r) : "r"(xi));
    return r;
}
__device__ __forceinline__ void ffma2(ull_t &d, ull_t a, ull_t b) {
    asm("fma.rn.f32x2 %0, %1, %2, %0;" : "+l"(d) : "l"(a), "l"(b));
}
__device__ __forceinline__ float tanh_mufu(float z) {
    float r;
    asm("tanh.approx.f32 %0, %1;" : "=f"(r) : "f"(z));
    return r;
}

// ---------------- Kernel 1: a = x @ w + bias -> A16 (fp16) ----------------
// R7's known-good FFMA2 body (93us with fp32 stores); epilogue now converts
// to half2 -> write bytes halve (128 -> 64 MB).
#define XS_LD 36
__global__ __launch_bounds__(256)
void mdrnn_gemm_kernel(const float* __restrict__ X, const float* __restrict__ W,
                       const float* __restrict__ Bias) {
    __shared__ float xs[128 * XS_LD];   // 18432 B
    __shared__ float ws[32 * 128];      // 16384 B

    const int tid   = threadIdx.x;
    const int mtile = blockIdx.x;                 // 2048 tiles of 128 rows
    const float* Xb = X + (size_t)mtile * 128 * PSIN;

    const int tidm = tid >> 4;
    const int tidn = tid & 15;
    const int m0   = tidm * 8;
    const int n0   = tidn * 2;

    ull_t acc[8][4];
#pragma unroll
    for (int mi = 0; mi < 8; mi++)
#pragma unroll
        for (int seg = 0; seg < 4; seg++) acc[mi][seg] = 0ULL;

    for (int kk = 0; kk < PSIN; kk += 32) {
        __syncthreads();
#pragma unroll
        for (int q = 0; q < 4; q++) {
            int id  = tid + 256 * q;
            int row = id >> 3;
            int kq  = id & 7;
            *(float4*)&xs[row * XS_LD + kq * 4] =
                *(const float4*)(Xb + row * PSIN + kk + kq * 4);
        }
#pragma unroll
        for (int q = 0; q < 4; q++) {
            int id = tid + 256 * q;
            int k  = id >> 5;
            int nq = id & 31;
            *(float4*)&ws[k * 128 + nq * 4] =
                *(const float4*)(W + (size_t)(kk + k) * PSOUT + nq * 4);
        }
        __syncthreads();

#pragma unroll 4
        for (int k = 0; k < 32; k++) {
            ull_t wv[4];
#pragma unroll
            for (int seg = 0; seg < 4; seg++)
                wv[seg] = *(const ull_t*)&ws[k * 128 + n0 + seg * 32];
#pragma unroll
            for (int mi = 0; mi < 8; mi++) {
                ull_t xp = pack2(xs[(m0 + mi) * XS_LD + k]);
#pragma unroll
                for (int seg = 0; seg < 4; seg++) ffma2(acc[mi][seg], xp, wv[seg]);
            }
        }
    }

    float2 bv[4];
#pragma unroll
    for (int seg = 0; seg < 4; seg++)
        bv[seg] = *(const float2*)(Bias + n0 + seg * 32);

#pragma unroll
    for (int mi = 0; mi < 8; mi++) {
        __half* out = A16 + ((size_t)mtile * 128 + m0 + mi) * PSOUT;
#pragma unroll
        for (int seg = 0; seg < 4; seg++) {
            uint2 u = *(uint2*)&acc[mi][seg];
            float ox = __uint_as_float(u.x) + bv[seg].x;
            float oy = __uint_as_float(u.y) + bv[seg].y;
            *(__half2*)(out + n0 + seg * 32) = __floats2half2_rn(ox, oy);
        }
    }
}

// ---------------- Kernel 2: 16-warp wavefront scan, fp16 a ----------------
// R12 structure (71.8us). 128 blocks x 512 threads; thread = (row i, s-quad).
// a now read from A16 as uint2 (4 halves = 8B), converted on consume; h
// written fp32 to d_out. DRAM read for a halves; ring regs halve too.
#define SDEPTH 8
__global__ __launch_bounds__(512)
void mdrnn_scan_kernel(const float* __restrict__ U, float* __restrict__ H) {
    __shared__ float4 sh[2][128][4];   // [buf][row][quad], 16KB

    const int tid = threadIdx.x;
    const int i   = tid >> 2;            // row 0..127
    const int qd  = tid & 3;             // s-quad 0..3
    const int b   = blockIdx.x >> 3;     // 0..15
    const int sc  = blockIdx.x & 7;      // 0..7
    const int s0  = sc * 16 + qd * 4;

    const float4 u0 = *(const float4*)(U + s0);
    const float4 u1 = *(const float4*)(U + PSOUT + s0);

    const size_t cellbase = (size_t)i * 262144 + (size_t)b * PSOUT + s0;
    const __half* Arow = A16 + cellbase;       // + j*2048
    float*        Hrow = H   + cellbase;       // + j*2048

    // seed ring: slot q <- a[j = q - i] (consumed at t = q), valid j only
    uint2 ra[SDEPTH];
#pragma unroll
    for (int q = 0; q < SDEPTH; q++) {
        int j = q - i;
        if ((unsigned)j < 128u)
            ra[q] = *(const uint2*)(Arow + (size_t)j * 2048);
    }

    float4 h = make_float4(0.f, 0.f, 0.f, 0.f);

#pragma unroll 8
    for (int t = 0; t < 256; t++) {
        const int j    = t - i;
        const int slot = t & (SDEPTH - 1);   // static under unroll 8

        // consume slot, refill independent of this iter's activity
        uint2 av = ra[slot];
        int jf = t + SDEPTH - i;
        if ((unsigned)jf < 128u)
            ra[slot] = *(const uint2*)(Arow + (size_t)jf * 2048);

        if ((unsigned)j < 128u) {
            float2 a01 = __half22float2(*(__half2*)&av.x);
            float2 a23 = __half22float2(*(__half2*)&av.y);

            float4 qa;
            if (i == 0) {
                qa = make_float4(0.f, 0.f, 0.f, 0.f);
            } else {
                qa = sh[(t & 1) ^ 1][i - 1][qd];
            }

            float4 z;
            z.x = fmaf(qa.x, u0.x, a01.x); z.x = fmaf(h.x, u1.x, z.x);
            z.y = fmaf(qa.y, u0.y, a01.y); z.y = fmaf(h.y, u1.y, z.y);
            z.z = fmaf(qa.z, u0.z, a23.x); z.z = fmaf(h.z, u1.z, z.z);
            z.w = fmaf(qa.w, u0.w, a23.y); z.w = fmaf(h.w, u1.w, z.w);

            h.x = tanh_mufu(z.x); h.y = tanh_mufu(z.y);
            h.z = tanh_mufu(z.z); h.w = tanh_mufu(z.w);

            sh[t & 1][i][qd] = h;
            *(float4*)(Hrow + (size_t)j * 2048) = h;
        }
        __syncthreads();
    }
}

// ---------------- launch ----------------
extern "C" void kernel_launch(void* const* d_in, const int* in_sizes, int n_in,
                              void* d_out, int out_size) {
    const float* X    = (const float*)d_in[0];   // (128,128,16,64)
    const float* W    = (const float*)d_in[1];   // (64,128)
    const float* U    = (const float*)d_in[2];   // (2,128)
    const float* Bias = (const float*)d_in[3];   // (128,)
    float* H = (float*)d_out;                    // (128,128,16,128)

    (void)in_sizes; (void)n_in; (void)out_size;

    mdrnn_gemm_kernel<<<2048, 256>>>(X, W, Bias);
    mdrnn_scan_kernel<<<128, 512>>>(U, H);
}